// round 16
// baseline (speedup 1.0000x reference)
#include <cuda_runtime.h>
#include <cuda_fp16.h>
#include <cstdint>

// ---------------- problem constants ----------------
constexpr int IN_F  = 4096;
constexpr int OUT_F = 4096;
constexpr int M_TOT = 8192;
constexpr int NB    = (OUT_F / 16) * (IN_F / 16);   // 65536 tiles

// ---------------- GEMM tiling ----------------
constexpr int BM = 128;
constexpr int BN = 256;
constexpr int BK = 64;                    // halfs of K per stage (128 B rows)
constexpr int STAGES = 4;
constexpr int NKT = IN_F / BK;            // 64 k-iterations
constexpr int ROW_B = 128;                // bytes per smem row
constexpr int A_TILE_B = BM * ROW_B;      // 16384
constexpr int B_TILE_B = BN * ROW_B;      // 32768
constexpr int STAGE_B  = A_TILE_B + B_TILE_B;       // 49152
constexpr int SMEM_TOTAL = STAGES * STAGE_B;        // 196608

// ---------------- scratch (fp16, natural k-order) ----------------
__device__ __half g_x[(size_t)M_TOT * IN_F];
__device__ __half g_W[(size_t)OUT_F * IN_F];

// ---------------- helpers ----------------
__device__ __forceinline__ uint32_t smem_to_u32(const void* p) {
    uint32_t a;
    asm("{ .reg .u64 t; cvta.to.shared.u64 t, %1; cvt.u32.u64 %0, t; }" : "=r"(a) : "l"(p));
    return a;
}
__device__ __forceinline__ void cp_async16(uint32_t dst, const void* src) {
    asm volatile("cp.async.cg.shared.global [%0], [%1], 16;" :: "r"(dst), "l"(src) : "memory");
}
#define CP_COMMIT() asm volatile("cp.async.commit_group;" ::: "memory")
#define CP_WAIT2()  asm volatile("cp.async.wait_group 2;" ::: "memory")

__device__ __forceinline__ void ldsm_x4(uint32_t* r, uint32_t addr) {
    asm volatile("ldmatrix.sync.aligned.m8n8.x4.shared.b16 {%0,%1,%2,%3}, [%4];"
                 : "=r"(r[0]), "=r"(r[1]), "=r"(r[2]), "=r"(r[3]) : "r"(addr));
}
__device__ __forceinline__ void mma_f16(float* c, const uint32_t* a, const uint32_t* b) {
    asm volatile(
        "mma.sync.aligned.m16n8k16.row.col.f32.f16.f16.f32 "
        "{%0,%1,%2,%3}, {%4,%5,%6,%7}, {%8,%9}, {%0,%1,%2,%3};"
        : "+f"(c[0]), "+f"(c[1]), "+f"(c[2]), "+f"(c[3])
        : "r"(a[0]), "r"(a[1]), "r"(a[2]), "r"(a[3]), "r"(b[0]), "r"(b[1]));
}

// ---------------------------------------------------------------------------
// Kernel 1 (fused, interleaved): blockIdx%3==0 -> FWHT (1/3), else decode (2/3).
// Ratio is exactly 32768 : 65536, so both kinds co-reside on the SMs.
// ---------------------------------------------------------------------------
constexpr int FWHT_BLOCKS = (M_TOT * (IN_F / 128)) / 8;   // 32768
constexpr int PREP_BLOCKS = FWHT_BLOCKS + NB;             // 98304

__global__ void __launch_bounds__(256) prep_kernel(const float* __restrict__ in,
                                                   __half* __restrict__ xout,
                                                   const int* __restrict__ trellis,
                                                   const float* __restrict__ tlut,
                                                   const float* __restrict__ scales,
                                                   __half* __restrict__ W) {
    const int bid = blockIdx.x;
    if (bid % 3 == 0) {
        // ---- FWHT part ----
        const int warp = ((bid / 3) << 3) | (threadIdx.x >> 5);
        const int lane = threadIdx.x & 31;
        const size_t base = (size_t)warp * 128;

        float4 v = reinterpret_cast<const float4*>(in + base)[lane];
        float a = v.x, b = v.y, c = v.z, d = v.w, t;
        t = a; a = a + b; b = t - b;
        t = c; c = c + d; d = t - d;
        t = a; a = a + c; c = t - c;
        t = b; b = b + d; d = t - d;
        #pragma unroll
        for (int mask = 1; mask <= 16; mask <<= 1) {
            float oa = __shfl_xor_sync(0xFFFFFFFFu, a, mask);
            float ob = __shfl_xor_sync(0xFFFFFFFFu, b, mask);
            float oc = __shfl_xor_sync(0xFFFFFFFFu, c, mask);
            float od = __shfl_xor_sync(0xFFFFFFFFu, d, mask);
            const bool hi = (lane & mask) != 0;
            a = hi ? (oa - a) : (a + oa);
            b = hi ? (ob - b) : (b + ob);
            c = hi ? (oc - c) : (c + oc);
            d = hi ? (od - d) : (d + od);
        }
        const float s = 0.08838834764831845f;
        __half2 h01 = __floats2half2_rn(a * s, b * s);
        __half2 h23 = __floats2half2_rn(c * s, d * s);
        uint2 pk = make_uint2(*reinterpret_cast<uint32_t*>(&h01),
                              *reinterpret_cast<uint32_t*>(&h23));
        reinterpret_cast<uint2*>(xout + base)[lane] = pk;
    } else {
        // ---- decode part ----
        const int nb = 2 * (bid / 3) + (bid % 3) - 1;
        const int t  = threadIdx.x;

        __shared__ uint32_t w[32];
        if (t < 32) w[t] = (uint32_t)trellis[nb * 32 + t] & 0xFFFFu;
        __syncthreads();

        const int p   = t << 1;
        const int i   = p >> 4;
        const int off = p & 15;
        const uint32_t s = (w[i] << 16) | w[(i + 1) & 31];
        const uint32_t state = (s >> (16 - off)) & 0xFFFFu;

        const float val = tlut[state];

        const int rb = nb >> 8;
        const int cb = nb & 255;
        const int tx = t >> 4;
        const int ty = t & 15;
        const int row = rb * 16 + tx;
        const int col = cb * 16 + ty;

        const float sc = scales[row * (IN_F / 128) + (col >> 7)];
        W[(size_t)row * IN_F + col] = __float2half_rn(val * sc);
    }
}

// ---------------------------------------------------------------------------
// Kernel 2: fp16 mma.sync GEMM, fragments software-pipelined ACROSS the kt
// boundary: barrier sits between ksp2 and ksp3 MMA batches; next stage's
// ksp0 fragments prefetched right after the barrier under ksp3's MMAs.
// ---------------------------------------------------------------------------
__global__ void __launch_bounds__(256, 1) gemm_mma_kernel(const __half* __restrict__ A,
                                                          const __half* __restrict__ B,
                                                          float* __restrict__ C) {
    extern __shared__ __half smem[];
    const uint32_t sbase = smem_to_u32(smem);

    const int tid  = threadIdx.x;
    const int lane = tid & 31;
    const int warp = tid >> 5;
    const int warp_m = warp >> 2;
    const int warp_n = warp & 3;

    // supertiles of 8 m-blocks x 16 n-blocks
    const int bid = blockIdx.x;
    const int sm_ = bid >> 7;
    const int w_  = bid & 127;
    const int bm  = ((sm_ << 3) | (w_ & 7)) * BM;
    const int bn  = (w_ >> 3) * BN;

    // ---- global -> smem (cp.async, XOR swizzle on 16B chunks) ----
    const int lrow   = tid >> 3;
    const int lchunk = tid & 7;
    const uint32_t wchunk = (uint32_t)((lchunk ^ (lrow & 7)) << 4);

    const __half* Ag = A + (size_t)(bm + lrow) * IN_F + (lchunk << 3);
    const __half* Bg = B + (size_t)(bn + lrow) * IN_F + (lchunk << 3);

    auto load_part = [&](int buf, int kt, int part) {
        const uint32_t sA = sbase + (uint32_t)buf * STAGE_B;
        const int koff = kt * BK;
        if (part == 0) {
            #pragma unroll
            for (int r = 0; r < 4; r++)
                cp_async16(sA + (uint32_t)(lrow + (r << 5)) * ROW_B + wchunk,
                           Ag + (size_t)(r << 5) * IN_F + koff);
        } else if (part == 1) {
            const uint32_t sB = sA + A_TILE_B;
            #pragma unroll
            for (int r = 0; r < 4; r++)
                cp_async16(sB + (uint32_t)(lrow + (r << 5)) * ROW_B + wchunk,
                           Bg + (size_t)(r << 5) * IN_F + koff);
        } else {
            const uint32_t sB = sA + A_TILE_B;
            #pragma unroll
            for (int r = 4; r < 8; r++)
                cp_async16(sB + (uint32_t)(lrow + (r << 5)) * ROW_B + wchunk,
                           Bg + (size_t)(r << 5) * IN_F + koff);
        }
    };

    // ---- ldmatrix addressing ----
    const int a_row  = warp_m * 64 + (((lane >> 3) & 1) << 3) + (lane & 7);
    const int a_kbit = lane >> 4;
    const int b_row  = warp_n * 64 + (((lane >> 4) & 1) << 3) + (lane & 7);
    const int b_kbit = (lane >> 3) & 1;
    const int sw     = lane & 7;

    const uint32_t a_base = (uint32_t)a_row * ROW_B;
    const uint32_t b_base = (uint32_t)b_row * ROW_B;

    float acc[4][8][4];
    #pragma unroll
    for (int i = 0; i < 4; i++)
        #pragma unroll
        for (int j = 0; j < 8; j++)
            #pragma unroll
            for (int r = 0; r < 4; r++) acc[i][j][r] = 0.0f;

    uint32_t af[2][4][4], bf[2][4][4];

    auto load_frags = [&](uint32_t stage_base, int ksp, int pb) {
        const uint32_t sA = stage_base;
        const uint32_t sB = stage_base + A_TILE_B;
        const uint32_t akx = (uint32_t)(((2 * ksp + a_kbit) ^ sw) << 4);
        const uint32_t bkx = (uint32_t)(((2 * ksp + b_kbit) ^ sw) << 4);
        #pragma unroll
        for (int mt = 0; mt < 4; mt++)
            ldsm_x4(af[pb][mt], sA + a_base + (uint32_t)(mt * 16) * ROW_B + akx);
        #pragma unroll
        for (int nn = 0; nn < 4; nn++)
            ldsm_x4(bf[pb][nn], sB + b_base + (uint32_t)(nn * 16) * ROW_B + bkx);
    };

    auto mma_batch = [&](int pb) {
        #pragma unroll
        for (int mt = 0; mt < 4; mt++)
            #pragma unroll
            for (int nn = 0; nn < 4; nn++) {
                mma_f16(acc[mt][2 * nn],     af[pb][mt], &bf[pb][nn][0]);
                mma_f16(acc[mt][2 * nn + 1], af[pb][mt], &bf[pb][nn][2]);
            }
    };

    // prologue: stages 0..2 in flight
    #pragma unroll
    for (int s = 0; s < STAGES - 1; s++) {
        load_part(s, s, 0);
        load_part(s, s, 1);
        load_part(s, s, 2);
        CP_COMMIT();
    }
    CP_WAIT2();              // stage 0 complete
    __syncthreads();
    load_frags(sbase, 0, 0); // (kt=0, ksp=0)

    const int lq = lane >> 2;
    const int lr = lane & 3;

    for (int kt = 0; kt < NKT; kt++) {
        const uint32_t stage = sbase + (uint32_t)(kt % STAGES) * STAGE_B;
        const bool pf   = (kt + STAGES - 1 < NKT);
        const int  pbuf = (kt + STAGES - 1) % STAGES;
        const int  pkt  = kt + STAGES - 1;

        // ksp 0..2: mma + preload next ksp frags + spread next-stage cp.asyncs
        #pragma unroll
        for (int ksp = 0; ksp < 3; ksp++) {
            const int cur = ksp & 1;
            load_frags(stage, ksp + 1, cur ^ 1);
            if (pf) load_part(pbuf, pkt, ksp);
            mma_batch(cur);
        }
        CP_COMMIT();

        if (kt + 1 < NKT) {
            // commits = 4+kt; wait 2 -> stages <= kt+1 complete
            CP_WAIT2();
            __syncthreads();
            // prefetch next kt's ksp0 frags (pb=0) while ksp3 (pb=1) computes
            load_frags(sbase + (uint32_t)((kt + 1) % STAGES) * STAGE_B, 0, 0);
        }
        mma_batch(1);   // ksp3
    }

    // epilogue
    const int crow = bm + warp_m * 64 + lq;
    const int ccol = bn + warp_n * 64 + 2 * lr;
    #pragma unroll
    for (int mt = 0; mt < 4; mt++) {
        #pragma unroll
        for (int nt = 0; nt < 8; nt++) {
            float* p0 = C + (size_t)(crow + mt * 16) * OUT_F + ccol + nt * 8;
            float* p1 = p0 + (size_t)8 * OUT_F;
            *reinterpret_cast<float2*>(p0) = make_float2(acc[mt][nt][0], acc[mt][nt][1]);
            *reinterpret_cast<float2*>(p1) = make_float2(acc[mt][nt][2], acc[mt][nt][3]);
        }
    }
}

// ---------------------------------------------------------------------------
extern "C" void kernel_launch(void* const* d_in, const int* in_sizes, int n_in,
                              void* d_out, int out_size) {
    const float* input   = (const float*)d_in[0];
    const int*   trellis = (const int*)  d_in[1];
    const float* tlut    = (const float*)d_in[2];
    const float* scales  = (const float*)d_in[3];
    float*       out     = (float*)d_out;

    __half* xbuf; __half* wbuf;
    cudaGetSymbolAddress((void**)&xbuf, g_x);
    cudaGetSymbolAddress((void**)&wbuf, g_W);

    prep_kernel<<<PREP_BLOCKS, 256>>>(input, xbuf, trellis, tlut, scales, wbuf);

    static bool attr_set = false;
    if (!attr_set) {
        cudaFuncSetAttribute(gemm_mma_kernel,
                             cudaFuncAttributeMaxDynamicSharedMemorySize, SMEM_TOTAL);
        attr_set = true;
    }
    const int nblocks = (M_TOT / BM) * (OUT_F / BN);   // 1024
    gemm_mma_kernel<<<nblocks, 256, SMEM_TOTAL>>>(xbuf, wbuf, out);
}

// round 17
// speedup vs baseline: 1.0039x; 1.0039x over previous
#include <cuda_runtime.h>
#include <cuda_fp16.h>
#include <cstdint>

// ---------------- problem constants ----------------
constexpr int IN_F  = 4096;
constexpr int OUT_F = 4096;
constexpr int M_TOT = 8192;
constexpr int NB    = (OUT_F / 16) * (IN_F / 16);   // 65536 tiles

// ---------------- GEMM tiling ----------------
constexpr int BM = 128;
constexpr int BN = 256;
constexpr int BK = 64;                    // halfs of K per stage (128 B rows)
constexpr int STAGES = 4;
constexpr int NKT = IN_F / BK;            // 64 k-iterations
constexpr int ROW_B = 128;                // bytes per smem row
constexpr int A_TILE_B = BM * ROW_B;      // 16384
constexpr int B_TILE_B = BN * ROW_B;      // 32768
constexpr int STAGE_B  = A_TILE_B + B_TILE_B;       // 49152
constexpr int SMEM_TOTAL = STAGES * STAGE_B;        // 196608

// ---------------- scratch (fp16, natural k-order) ----------------
__device__ __half g_x[(size_t)M_TOT * IN_F];
__device__ __half g_W[(size_t)OUT_F * IN_F];

// ---------------- helpers ----------------
__device__ __forceinline__ uint32_t smem_to_u32(const void* p) {
    uint32_t a;
    asm("{ .reg .u64 t; cvta.to.shared.u64 t, %1; cvt.u32.u64 %0, t; }" : "=r"(a) : "l"(p));
    return a;
}
__device__ __forceinline__ void cp_async16(uint32_t dst, const void* src) {
    asm volatile("cp.async.cg.shared.global [%0], [%1], 16;" :: "r"(dst), "l"(src) : "memory");
}
#define CP_COMMIT() asm volatile("cp.async.commit_group;" ::: "memory")
#define CP_WAIT2()  asm volatile("cp.async.wait_group 2;" ::: "memory")

__device__ __forceinline__ void ldsm_x4(uint32_t* r, uint32_t addr) {
    asm volatile("ldmatrix.sync.aligned.m8n8.x4.shared.b16 {%0,%1,%2,%3}, [%4];"
                 : "=r"(r[0]), "=r"(r[1]), "=r"(r[2]), "=r"(r[3]) : "r"(addr));
}
__device__ __forceinline__ void mma_f16(float* c, const uint32_t* a, const uint32_t* b) {
    asm volatile(
        "mma.sync.aligned.m16n8k16.row.col.f32.f16.f16.f32 "
        "{%0,%1,%2,%3}, {%4,%5,%6,%7}, {%8,%9}, {%0,%1,%2,%3};"
        : "+f"(c[0]), "+f"(c[1]), "+f"(c[2]), "+f"(c[3])
        : "r"(a[0]), "r"(a[1]), "r"(a[2]), "r"(a[3]), "r"(b[0]), "r"(b[1]));
}

// ---------------------------------------------------------------------------
// Kernel 1 (fused, interleaved): blockIdx%3==0 -> FWHT (1/3), else decode (2/3).
// Ratio is exactly 32768 : 65536, so both kinds co-reside on the SMs.
// ---------------------------------------------------------------------------
constexpr int FWHT_BLOCKS = (M_TOT * (IN_F / 128)) / 8;   // 32768
constexpr int PREP_BLOCKS = FWHT_BLOCKS + NB;             // 98304

__global__ void __launch_bounds__(256) prep_kernel(const float* __restrict__ in,
                                                   __half* __restrict__ xout,
                                                   const int* __restrict__ trellis,
                                                   const float* __restrict__ tlut,
                                                   const float* __restrict__ scales,
                                                   __half* __restrict__ W) {
    const int bid = blockIdx.x;
    if (bid % 3 == 0) {
        // ---- FWHT part ----
        const int warp = ((bid / 3) << 3) | (threadIdx.x >> 5);
        const int lane = threadIdx.x & 31;
        const size_t base = (size_t)warp * 128;

        float4 v = reinterpret_cast<const float4*>(in + base)[lane];
        float a = v.x, b = v.y, c = v.z, d = v.w, t;
        t = a; a = a + b; b = t - b;
        t = c; c = c + d; d = t - d;
        t = a; a = a + c; c = t - c;
        t = b; b = b + d; d = t - d;
        #pragma unroll
        for (int mask = 1; mask <= 16; mask <<= 1) {
            float oa = __shfl_xor_sync(0xFFFFFFFFu, a, mask);
            float ob = __shfl_xor_sync(0xFFFFFFFFu, b, mask);
            float oc = __shfl_xor_sync(0xFFFFFFFFu, c, mask);
            float od = __shfl_xor_sync(0xFFFFFFFFu, d, mask);
            const bool hi = (lane & mask) != 0;
            a = hi ? (oa - a) : (a + oa);
            b = hi ? (ob - b) : (b + ob);
            c = hi ? (oc - c) : (c + oc);
            d = hi ? (od - d) : (d + od);
        }
        const float s = 0.08838834764831845f;
        __half2 h01 = __floats2half2_rn(a * s, b * s);
        __half2 h23 = __floats2half2_rn(c * s, d * s);
        uint2 pk = make_uint2(*reinterpret_cast<uint32_t*>(&h01),
                              *reinterpret_cast<uint32_t*>(&h23));
        reinterpret_cast<uint2*>(xout + base)[lane] = pk;
    } else {
        // ---- decode part ----
        const int nb = 2 * (bid / 3) + (bid % 3) - 1;
        const int t  = threadIdx.x;

        __shared__ uint32_t w[32];
        if (t < 32) w[t] = (uint32_t)trellis[nb * 32 + t] & 0xFFFFu;
        __syncthreads();

        const int p   = t << 1;
        const int i   = p >> 4;
        const int off = p & 15;
        const uint32_t s = (w[i] << 16) | w[(i + 1) & 31];
        const uint32_t state = (s >> (16 - off)) & 0xFFFFu;

        const float val = tlut[state];

        const int rb = nb >> 8;
        const int cb = nb & 255;
        const int tx = t >> 4;
        const int ty = t & 15;
        const int row = rb * 16 + tx;
        const int col = cb * 16 + ty;

        const float sc = scales[row * (IN_F / 128) + (col >> 7)];
        W[(size_t)row * IN_F + col] = __float2half_rn(val * sc);
    }
}

// ---------------------------------------------------------------------------
// Kernel 2: fp16 mma.sync GEMM, fragments software-pipelined ACROSS the kt
// boundary: barrier sits between ksp2 and ksp3 MMA batches; next stage's
// ksp0 fragments prefetched right after the barrier under ksp3's MMAs.
// ---------------------------------------------------------------------------
__global__ void __launch_bounds__(256, 1) gemm_mma_kernel(const __half* __restrict__ A,
                                                          const __half* __restrict__ B,
                                                          float* __restrict__ C) {
    extern __shared__ __half smem[];
    const uint32_t sbase = smem_to_u32(smem);

    const int tid  = threadIdx.x;
    const int lane = tid & 31;
    const int warp = tid >> 5;
    const int warp_m = warp >> 2;
    const int warp_n = warp & 3;

    // supertiles of 8 m-blocks x 16 n-blocks
    const int bid = blockIdx.x;
    const int sm_ = bid >> 7;
    const int w_  = bid & 127;
    const int bm  = ((sm_ << 3) | (w_ & 7)) * BM;
    const int bn  = (w_ >> 3) * BN;

    // ---- global -> smem (cp.async, XOR swizzle on 16B chunks) ----
    const int lrow   = tid >> 3;
    const int lchunk = tid & 7;
    const uint32_t wchunk = (uint32_t)((lchunk ^ (lrow & 7)) << 4);

    const __half* Ag = A + (size_t)(bm + lrow) * IN_F + (lchunk << 3);
    const __half* Bg = B + (size_t)(bn + lrow) * IN_F + (lchunk << 3);

    auto load_part = [&](int buf, int kt, int part) {
        const uint32_t sA = sbase + (uint32_t)buf * STAGE_B;
        const int koff = kt * BK;
        if (part == 0) {
            #pragma unroll
            for (int r = 0; r < 4; r++)
                cp_async16(sA + (uint32_t)(lrow + (r << 5)) * ROW_B + wchunk,
                           Ag + (size_t)(r << 5) * IN_F + koff);
        } else if (part == 1) {
            const uint32_t sB = sA + A_TILE_B;
            #pragma unroll
            for (int r = 0; r < 4; r++)
                cp_async16(sB + (uint32_t)(lrow + (r << 5)) * ROW_B + wchunk,
                           Bg + (size_t)(r << 5) * IN_F + koff);
        } else {
            const uint32_t sB = sA + A_TILE_B;
            #pragma unroll
            for (int r = 4; r < 8; r++)
                cp_async16(sB + (uint32_t)(lrow + (r << 5)) * ROW_B + wchunk,
                           Bg + (size_t)(r << 5) * IN_F + koff);
        }
    };

    // ---- ldmatrix addressing ----
    const int a_row  = warp_m * 64 + (((lane >> 3) & 1) << 3) + (lane & 7);
    const int a_kbit = lane >> 4;
    const int b_row  = warp_n * 64 + (((lane >> 4) & 1) << 3) + (lane & 7);
    const int b_kbit = (lane >> 3) & 1;
    const int sw     = lane & 7;

    const uint32_t a_base = (uint32_t)a_row * ROW_B;
    const uint32_t b_base = (uint32_t)b_row * ROW_B;

    float acc[4][8][4];
    #pragma unroll
    for (int i = 0; i < 4; i++)
        #pragma unroll
        for (int j = 0; j < 8; j++)
            #pragma unroll
            for (int r = 0; r < 4; r++) acc[i][j][r] = 0.0f;

    uint32_t af[2][4][4], bf[2][4][4];

    auto load_frags = [&](uint32_t stage_base, int ksp, int pb) {
        const uint32_t sA = stage_base;
        const uint32_t sB = stage_base + A_TILE_B;
        const uint32_t akx = (uint32_t)(((2 * ksp + a_kbit) ^ sw) << 4);
        const uint32_t bkx = (uint32_t)(((2 * ksp + b_kbit) ^ sw) << 4);
        #pragma unroll
        for (int mt = 0; mt < 4; mt++)
            ldsm_x4(af[pb][mt], sA + a_base + (uint32_t)(mt * 16) * ROW_B + akx);
        #pragma unroll
        for (int nn = 0; nn < 4; nn++)
            ldsm_x4(bf[pb][nn], sB + b_base + (uint32_t)(nn * 16) * ROW_B + bkx);
    };

    auto mma_batch = [&](int pb) {
        #pragma unroll
        for (int mt = 0; mt < 4; mt++)
            #pragma unroll
            for (int nn = 0; nn < 4; nn++) {
                mma_f16(acc[mt][2 * nn],     af[pb][mt], &bf[pb][nn][0]);
                mma_f16(acc[mt][2 * nn + 1], af[pb][mt], &bf[pb][nn][2]);
            }
    };

    // prologue: stages 0..2 in flight
    #pragma unroll
    for (int s = 0; s < STAGES - 1; s++) {
        load_part(s, s, 0);
        load_part(s, s, 1);
        load_part(s, s, 2);
        CP_COMMIT();
    }
    CP_WAIT2();              // stage 0 complete
    __syncthreads();
    load_frags(sbase, 0, 0); // (kt=0, ksp=0)

    const int lq = lane >> 2;
    const int lr = lane & 3;

    for (int kt = 0; kt < NKT; kt++) {
        const uint32_t stage = sbase + (uint32_t)(kt % STAGES) * STAGE_B;
        const bool pf   = (kt + STAGES - 1 < NKT);
        const int  pbuf = (kt + STAGES - 1) % STAGES;
        const int  pkt  = kt + STAGES - 1;

        // ksp 0..2: mma + preload next ksp frags + spread next-stage cp.asyncs
        #pragma unroll
        for (int ksp = 0; ksp < 3; ksp++) {
            const int cur = ksp & 1;
            load_frags(stage, ksp + 1, cur ^ 1);
            if (pf) load_part(pbuf, pkt, ksp);
            mma_batch(cur);
        }
        CP_COMMIT();

        if (kt + 1 < NKT) {
            // commits = 4+kt; wait 2 -> stages <= kt+1 complete
            CP_WAIT2();
            __syncthreads();
            // prefetch next kt's ksp0 frags (pb=0) while ksp3 (pb=1) computes
            load_frags(sbase + (uint32_t)((kt + 1) % STAGES) * STAGE_B, 0, 0);
        }
        mma_batch(1);   // ksp3
    }

    // epilogue
    const int crow = bm + warp_m * 64 + lq;
    const int ccol = bn + warp_n * 64 + 2 * lr;
    #pragma unroll
    for (int mt = 0; mt < 4; mt++) {
        #pragma unroll
        for (int nt = 0; nt < 8; nt++) {
            float* p0 = C + (size_t)(crow + mt * 16) * OUT_F + ccol + nt * 8;
            float* p1 = p0 + (size_t)8 * OUT_F;
            *reinterpret_cast<float2*>(p0) = make_float2(acc[mt][nt][0], acc[mt][nt][1]);
            *reinterpret_cast<float2*>(p1) = make_float2(acc[mt][nt][2], acc[mt][nt][3]);
        }
    }
}

// ---------------------------------------------------------------------------
extern "C" void kernel_launch(void* const* d_in, const int* in_sizes, int n_in,
                              void* d_out, int out_size) {
    const float* input   = (const float*)d_in[0];
    const int*   trellis = (const int*)  d_in[1];
    const float* tlut    = (const float*)d_in[2];
    const float* scales  = (const float*)d_in[3];
    float*       out     = (float*)d_out;

    __half* xbuf; __half* wbuf;
    cudaGetSymbolAddress((void**)&xbuf, g_x);
    cudaGetSymbolAddress((void**)&wbuf, g_W);

    prep_kernel<<<PREP_BLOCKS, 256>>>(input, xbuf, trellis, tlut, scales, wbuf);

    static bool attr_set = false;
    if (!attr_set) {
        cudaFuncSetAttribute(gemm_mma_kernel,
                             cudaFuncAttributeMaxDynamicSharedMemorySize, SMEM_TOTAL);
        attr_set = true;
    }
    const int nblocks = (M_TOT / BM) * (OUT_F / BN);   // 1024
    gemm_mma_kernel<<<nblocks, 256, SMEM_TOTAL>>>(xbuf, wbuf, out);
}